// round 12
// baseline (speedup 1.0000x reference)
#include <cuda_runtime.h>
#include <stdint.h>

// fine_data: out[f*64 + c4*4 .. +3] = coarse_data[(f>>3)*64 + c4*4 ..]
// one thread per float4 of output data region.
__global__ void __launch_bounds__(256) upsample_data_kernel(
    const float4* __restrict__ coarse, float4* __restrict__ out, long total_f4)
{
    long g = (long)blockIdx.x * blockDim.x + threadIdx.x;
    if (g >= total_f4) return;
    long f = g >> 4;          // fine voxel index
    int  c = (int)(g & 15);   // float4 chunk within 64-channel row
    long n = f >> 3;          // coarse voxel index
    out[g] = coarse[n * 16 + c];
}

// fine_ijk: one thread per output element, written as FLOAT (harness d_out is
// a single float32 buffer; reference int output is cast to float).
// offsets order (meshgrid ij): o -> (i,j,k) = (o>>2, (o>>1)&1, o&1)
__global__ void __launch_bounds__(256) upsample_ijk_kernel(
    const int* __restrict__ ijk, float* __restrict__ out, long total_elems)
{
    long e = (long)blockIdx.x * blockDim.x + threadIdx.x;
    if (e >= total_elems) return;
    long f = e / 3;           // fine voxel index
    int  d = (int)(e - f * 3);
    long n = f >> 3;          // coarse voxel
    int  o = (int)(f & 7);    // sub-voxel index
    int  off = (o >> (2 - d)) & 1;  // d=0 -> bit2, d=1 -> bit1, d=2 -> bit0
    out[e] = (float)(ijk[n * 3 + d] * 2 + off);
}

extern "C" void kernel_launch(void* const* d_in, const int* in_sizes, int n_in,
                              void* d_out, int out_size)
{
    const float* coarse_data = (const float*)d_in[0];
    const int*   coarse_ijk  = (const int*)d_in[1];

    long n_coarse = in_sizes[1] / 3;          // 262144
    long n_fine   = n_coarse * 8;
    long data_elems = n_fine * 64;            // fine_data region (float32)
    long data_f4    = data_elems / 4;

    {
        long blocks = (data_f4 + 255) / 256;
        upsample_data_kernel<<<(unsigned)blocks, 256>>>(
            (const float4*)coarse_data, (float4*)d_out, data_f4);
    }

    long remaining = (long)out_size - data_elems;
    if (remaining > 0) {
        long ijk_elems = remaining < n_fine * 3 ? remaining : n_fine * 3;
        float* ijk_out = (float*)d_out + data_elems;
        long blocks = (ijk_elems + 255) / 256;
        upsample_ijk_kernel<<<(unsigned)blocks, 256>>>(
            coarse_ijk, ijk_out, ijk_elems);
    }
}

// round 14
// speedup vs baseline: 1.3357x; 1.3357x over previous
#include <cuda_runtime.h>
#include <stdint.h>

// Fused kernel.
// Blocks [0, ijk_blocks): one thread per coarse voxel -> 24 ijk floats (6 x float4).
// Blocks [ijk_blocks, ...): one thread per coarse float4 -> 8 replicated stores.
__global__ void __launch_bounds__(256) upsample_fused_kernel(
    const float4* __restrict__ coarse,   // coarse_data as float4 [n_coarse*16]
    const int*    __restrict__ ijk,      // coarse_ijk [n_coarse*3]
    float4*       __restrict__ out_data, // fine_data region as float4
    float4*       __restrict__ out_ijk,  // fine_ijk region (float, 16B-aligned)
    int n_coarse, int ijk_blocks)
{
    int b = blockIdx.x;
    if (b < ijk_blocks) {
        int n = b * 256 + threadIdx.x;
        if (n >= n_coarse) return;
        int vi = ijk[3 * n + 0];
        int vj = ijk[3 * n + 1];
        int vk = ijk[3 * n + 2];
        float x  = (float)(2 * vi), x1 = x + 1.0f;
        float y  = (float)(2 * vj), y1 = y + 1.0f;
        float z  = (float)(2 * vk), z1 = z + 1.0f;
        // 24 floats, o = i*4+j*2+k order: (x|x1, y|y1, z|z1)
        float4 q0 = make_float4(x,  y,  z,  x );
        float4 q1 = make_float4(y,  z1, x,  y1);
        float4 q2 = make_float4(z,  x,  y1, z1);
        float4 q3 = make_float4(x1, y,  z,  x1);
        float4 q4 = make_float4(y,  z1, x1, y1);
        float4 q5 = make_float4(z,  x1, y1, z1);
        float4* dst = out_ijk + (long)n * 6;   // 24 floats = 6 float4
        __stcs(dst + 0, q0);
        __stcs(dst + 1, q1);
        __stcs(dst + 2, q2);
        __stcs(dst + 3, q3);
        __stcs(dst + 4, q4);
        __stcs(dst + 5, q5);
    } else {
        long t = (long)(b - ijk_blocks) * 256 + threadIdx.x; // coarse float4 idx
        long total = (long)n_coarse * 16;
        if (t >= total) return;
        long n = t >> 4;          // coarse voxel
        int  c = (int)(t & 15);   // float4 chunk within 64-channel row
        float4 val = __ldcs(&coarse[t]);
        // fine rows for voxel n occupy float4 [n*128, n*128+128)
        float4* dst = out_data + n * 128 + c;
        #pragma unroll
        for (int k = 0; k < 8; k++)
            __stcs(dst + k * 16, val);
    }
}

// Fallback scalar ijk kernel for a partial ijk region (defensive only).
__global__ void __launch_bounds__(256) upsample_ijk_scalar_kernel(
    const int* __restrict__ ijk, float* __restrict__ out, long total_elems)
{
    long e = (long)blockIdx.x * blockDim.x + threadIdx.x;
    if (e >= total_elems) return;
    long f = e / 3;
    int  d = (int)(e - f * 3);
    long n = f >> 3;
    int  o = (int)(f & 7);
    int  off = (o >> (2 - d)) & 1;
    out[e] = (float)(ijk[n * 3 + d] * 2 + off);
}

extern "C" void kernel_launch(void* const* d_in, const int* in_sizes, int n_in,
                              void* d_out, int out_size)
{
    const float* coarse_data = (const float*)d_in[0];
    const int*   coarse_ijk  = (const int*)d_in[1];

    long n_coarse   = in_sizes[1] / 3;       // 262144
    long n_fine     = n_coarse * 8;
    long data_elems = n_fine * 64;           // fine_data floats
    long remaining  = (long)out_size - data_elems;
    bool full_ijk   = (remaining >= n_fine * 3);

    int data_blocks = (int)((n_coarse * 16 + 255) / 256);
    int ijk_blocks  = full_ijk ? (int)((n_coarse + 255) / 256) : 0;

    float* ijk_out = (float*)d_out + data_elems;

    upsample_fused_kernel<<<ijk_blocks + data_blocks, 256>>>(
        (const float4*)coarse_data, coarse_ijk,
        (float4*)d_out, (float4*)ijk_out,
        (int)n_coarse, ijk_blocks);

    if (!full_ijk && remaining > 0) {
        long blocks = (remaining + 255) / 256;
        upsample_ijk_scalar_kernel<<<(unsigned)blocks, 256>>>(
            coarse_ijk, ijk_out, remaining);
    }
}